// round 1
// baseline (speedup 1.0000x reference)
#include <cuda_runtime.h>
#include <math.h>

// Composed effective weights: w_eff[0..6] (7x1), w_eff[7] = b_eff
__device__ float g_weff[8];

// ---------------------------------------------------------------------------
// Kernel 1: collapse the 5 linear layers into one 7->1 affine map.
// Single thread; ~200 flops total. Dims: 7,5,4,3,2,1.
// ---------------------------------------------------------------------------
__global__ void compose_weights_kernel(
    const float* __restrict__ W1, const float* __restrict__ b1,
    const float* __restrict__ W2, const float* __restrict__ b2,
    const float* __restrict__ W3, const float* __restrict__ b3,
    const float* __restrict__ W4, const float* __restrict__ b4,
    const float* __restrict__ W5, const float* __restrict__ b5)
{
    if (threadIdx.x != 0 || blockIdx.x != 0) return;

    const int dims[6] = {7, 5, 4, 3, 2, 1};
    const float* Ws[5] = {W1, W2, W3, W4, W5};
    const float* bs[5] = {b1, b2, b3, b4, b5};

    // M starts as W1 (7 x 5), multiply through: M = M @ W_{k}
    float M[7 * 7];
    int rows = dims[0], cols = dims[1];
    for (int i = 0; i < rows; i++)
        for (int j = 0; j < cols; j++)
            M[i * cols + j] = W1[i * cols + j];

    float tmp[7 * 7];
    for (int k = 1; k < 5; k++) {
        int inner = dims[k], nc = dims[k + 1];
        const float* Wk = Ws[k];
        for (int i = 0; i < rows; i++) {
            for (int j = 0; j < nc; j++) {
                float s = 0.f;
                for (int p = 0; p < inner; p++)
                    s += M[i * cols + p] * Wk[p * nc + j];
                tmp[i * nc + j] = s;
            }
        }
        cols = nc;
        for (int i = 0; i < rows * cols; i++) M[i] = tmp[i];
    }
    // M is now 7 x 1

    // bias: v = b1; v = v@W_{k+1} + b_{k+1}
    float v[7];
    int vn = dims[1];
    for (int j = 0; j < vn; j++) v[j] = bs[0][j];
    float vt[7];
    for (int k = 1; k < 5; k++) {
        int nc = dims[k + 1];
        const float* Wk = Ws[k];
        for (int j = 0; j < nc; j++) {
            float s = bs[k][j];
            for (int p = 0; p < vn; p++)
                s += v[p] * Wk[p * nc + j];
            vt[j] = s;
        }
        vn = nc;
        for (int j = 0; j < vn; j++) v[j] = vt[j];
    }

    for (int i = 0; i < 7; i++) g_weff[i] = M[i];
    g_weff[7] = v[0];
}

// ---------------------------------------------------------------------------
// Kernel 2: streaming sigmoid(X @ w_eff + b_eff).
// Each thread: 4 rows = 28 floats = 7 aligned float4 loads, 1 float4 store.
// ---------------------------------------------------------------------------
__global__ void __launch_bounds__(256)
mlp_stream_kernel(const float* __restrict__ X, float* __restrict__ out, int nrows)
{
    int t = blockIdx.x * blockDim.x + threadIdx.x;
    long long row0 = (long long)t * 4;
    if (row0 >= nrows) return;

    // broadcast loads, L1/L2 cached
    float w0 = g_weff[0], w1 = g_weff[1], w2 = g_weff[2], w3 = g_weff[3];
    float w4 = g_weff[4], w5 = g_weff[5], w6 = g_weff[6], be = g_weff[7];

    float r[4];

    if (row0 + 4 <= nrows) {
        // 28 consecutive floats, base = 112*t bytes -> 16B aligned
        const float4* Xv = reinterpret_cast<const float4*>(X + row0 * 7);
        float4 p0 = Xv[0], p1 = Xv[1], p2 = Xv[2], p3 = Xv[3];
        float4 p4 = Xv[4], p5 = Xv[5], p6 = Xv[6];

        float f[28];
        f[0]=p0.x; f[1]=p0.y; f[2]=p0.z; f[3]=p0.w;
        f[4]=p1.x; f[5]=p1.y; f[6]=p1.z; f[7]=p1.w;
        f[8]=p2.x; f[9]=p2.y; f[10]=p2.z; f[11]=p2.w;
        f[12]=p3.x; f[13]=p3.y; f[14]=p3.z; f[15]=p3.w;
        f[16]=p4.x; f[17]=p4.y; f[18]=p4.z; f[19]=p4.w;
        f[20]=p5.x; f[21]=p5.y; f[22]=p5.z; f[23]=p5.w;
        f[24]=p6.x; f[25]=p6.y; f[26]=p6.z; f[27]=p6.w;

        #pragma unroll
        for (int r4 = 0; r4 < 4; r4++) {
            const float* x = f + r4 * 7;
            float z = be;
            z = fmaf(x[0], w0, z);
            z = fmaf(x[1], w1, z);
            z = fmaf(x[2], w2, z);
            z = fmaf(x[3], w3, z);
            z = fmaf(x[4], w4, z);
            z = fmaf(x[5], w5, z);
            z = fmaf(x[6], w6, z);
            r[r4] = 1.0f / (1.0f + __expf(-z));
        }

        float4 o;
        o.x = r[0]; o.y = r[1]; o.z = r[2]; o.w = r[3];
        reinterpret_cast<float4*>(out + row0)[0] = o;
    } else {
        // tail (not hit for nrows % 4 == 0, kept for safety)
        for (long long rr = row0; rr < nrows; rr++) {
            const float* x = X + rr * 7;
            float z = be;
            z = fmaf(x[0], w0, z);
            z = fmaf(x[1], w1, z);
            z = fmaf(x[2], w2, z);
            z = fmaf(x[3], w3, z);
            z = fmaf(x[4], w4, z);
            z = fmaf(x[5], w5, z);
            z = fmaf(x[6], w6, z);
            out[rr] = 1.0f / (1.0f + __expf(-z));
        }
    }
}

extern "C" void kernel_launch(void* const* d_in, const int* in_sizes, int n_in,
                              void* d_out, int out_size)
{
    const float* X  = (const float*)d_in[0];
    const float* W1 = (const float*)d_in[1];
    const float* b1 = (const float*)d_in[2];
    const float* W2 = (const float*)d_in[3];
    const float* b2 = (const float*)d_in[4];
    const float* W3 = (const float*)d_in[5];
    const float* b3 = (const float*)d_in[6];
    const float* W4 = (const float*)d_in[7];
    const float* b4 = (const float*)d_in[8];
    const float* W5 = (const float*)d_in[9];
    const float* b5 = (const float*)d_in[10];
    float* out = (float*)d_out;

    int nrows = in_sizes[0] / 7;

    compose_weights_kernel<<<1, 32>>>(W1, b1, W2, b2, W3, b3, W4, b4, W5, b5);

    int nthreads = (nrows + 3) / 4;
    int blocks = (nthreads + 255) / 256;
    mlp_stream_kernel<<<blocks, 256>>>(X, out, nrows);
}